// round 15
// baseline (speedup 1.0000x reference)
#include <cuda_runtime.h>
#include <math.h>

// Problem constants
#define NB   2
#define NS   2048
#define NH   16
#define ND   64
#define NHID 1024
#define NCK  64      // chunk size
#define NNC  32      // chunks per sequence
#define NBH  32      // NB*NH
#define PST  68      // padded smem row stride (floats)

typedef unsigned long long u64;

// Scratch (static device globals -- no allocation allowed)
__device__ float4 g_tab[NS * 32];              // xPos table: (cos*sc, sin*sc, cos/sc, sin/sc)
__device__ float  g_qr[NBH * NS * ND];         // rotated Q, [bh][s][d]
__device__ float  g_kr[NBH * NS * ND];         // rotated K, [bh][s][d]
__device__ float  g_A [NBH * NNC * ND * ND];   // per-chunk state contributions
__device__ float  g_St[NBH * NNC * ND * ND];   // prefix-scanned states (state BEFORE chunk c)

__device__ __forceinline__ double head_lg(int h) {
    const double L0 = -3.4657359027997265;   // log(1/32)
    const double L1 = -6.2383246250395075;   // log(1/512)
    double g = 1.0 - exp(L0 + (L1 - L0) * ((double)h / 15.0));
    return log(g);
}

// ---- packed f32x2 helpers ----
__device__ __forceinline__ u64 pk2(float x) {
    unsigned xi = __float_as_uint(x);
    u64 r; asm("mov.b64 %0, {%1, %1};" : "=l"(r) : "r"(xi)); return r;
}
__device__ __forceinline__ u64 ffma2(u64 a, u64 b, u64 c) {
    u64 d; asm("fma.rn.f32x2 %0, %1, %2, %3;" : "=l"(d) : "l"(a), "l"(b), "l"(c)); return d;
}
__device__ __forceinline__ float2 up2(u64 v) {
    unsigned lo, hi; asm("mov.b64 {%0, %1}, %2;" : "=r"(lo), "=r"(hi) : "l"(v));
    return make_float2(__uint_as_float(lo), __uint_as_float(hi));
}

// ---------------------------------------------------------------------------
// Kernel 0: xPos table. tab[s][i] = (cos*sc, sin*sc, cos/sc, sin/sc)
// ---------------------------------------------------------------------------
__global__ __launch_bounds__(256)
void table_kernel() {
    int idx = blockIdx.x * 256 + threadIdx.x;   // [0, 2048*32)
    int i = idx & 31;
    int s = idx >> 5;
    float invf = (float)(1.0 / pow(10000.0, (double)i / 32.0));
    float bs   = (2.0f * (float)i + 25.6f) / 89.6f;   // (2i + 0.4*64)/(1.4*64)
    float pos  = (float)s;
    float sn, cs;
    sincosf(pos * invf, &sn, &cs);
    float sc = powf(bs, pos * (1.0f / 512.0f));
    float iv = 1.0f / sc;
    g_tab[idx] = make_float4(cs * sc, sn * sc, cs * iv, sn * iv);
}

// ---------------------------------------------------------------------------
// Kernel 0.5: rope_lite v2 -- 4 floats per thread (float4 in/out), table-based.
// ---------------------------------------------------------------------------
__global__ __launch_bounds__(256)
void rope_lite_kernel(const float* __restrict__ Q, const float* __restrict__ K) {
    int idx = blockIdx.x * 256 + threadIdx.x;  // [0, NBH*NS*16)
    int iq = idx & 15;                          // quad index, d0 = 4*iq
    int s  = (idx >> 4) & (NS - 1);
    int bh = idx >> 15;
    int h  = bh & (NH - 1);
    int b  = bh >> 4;
    int d0 = 4 * iq;

    float4 t0 = g_tab[(s << 5) + 2 * iq];      // pairs 2iq, 2iq+1
    float4 t1 = g_tab[(s << 5) + 2 * iq + 1];

    int gin = (b * NS + s) * NHID + h * ND + d0;
    float4 q = *(const float4*)(Q + gin);
    float4 k = *(const float4*)(K + gin);

    float4 qo, ko;
    qo.x = q.x * t0.x - q.y * t0.y;
    qo.y = q.y * t0.x + q.x * t0.y;
    qo.z = q.z * t1.x - q.w * t1.y;
    qo.w = q.w * t1.x + q.z * t1.y;
    ko.x = k.x * t0.z - k.y * t0.w;
    ko.y = k.y * t0.z + k.x * t0.w;
    ko.z = k.z * t1.z - k.w * t1.w;
    ko.w = k.w * t1.z + k.z * t1.w;

    int gout = (bh * NS + s) * ND + d0;
    *(float4*)(g_qr + gout) = qo;
    *(float4*)(g_kr + gout) = ko;
}

// ---------------------------------------------------------------------------
// Kernel 1: A_c[d][e] = sum_j gamma^(C-j) k'[j][d] v[j][e]
// f32x2 body; A-operand is contiguous in ks -> single float4 LDS per iter.
// ---------------------------------------------------------------------------
__global__ __launch_bounds__(256)
void passA_kernel(const float* __restrict__ V) {
    __shared__ float ks[NCK * PST];
    __shared__ float vs[NCK * PST];
    __shared__ float wr[NCK];

    int c = blockIdx.x, h = blockIdx.y, b = blockIdx.z;
    int bh = b * NH + h;
    int tid = threadIdx.x;

    if (tid < NCK) {
        double lg = head_lg(h);
        wr[tid] = (float)exp(lg * (double)(NCK - tid));   // gamma^(C-j)
    }
    __syncthreads();

    int c0 = c * NCK;
    const float* kg = g_kr + (bh * NS + c0) * ND;
    const float* vg = V + (b * NS + c0) * NHID + h * ND;

#pragma unroll
    for (int t = 0; t < 16; ++t) {
        int idx = tid + t * 256;
        int r = idx >> 6, d = idx & 63;
        ks[r * PST + d] = kg[r * ND + d] * wr[r];
        vs[r * PST + d] = vg[r * NHID + d];
    }
    __syncthreads();

    int ty = tid >> 4, tx = tid & 15;
    u64 acc[4][2];
#pragma unroll
    for (int r = 0; r < 4; ++r) { acc[r][0] = 0ull; acc[r][1] = 0ull; }

#pragma unroll 8
    for (int j = 0; j < NCK; ++j) {
        float4 ka = *(const float4*)(ks + j * PST + 4 * ty);
        u64 a0 = pk2(ka.x), a1 = pk2(ka.y), a2 = pk2(ka.z), a3 = pk2(ka.w);
        ulonglong2 bb = *(const ulonglong2*)(vs + j * PST + 4 * tx);
        acc[0][0] = ffma2(a0, bb.x, acc[0][0]); acc[0][1] = ffma2(a0, bb.y, acc[0][1]);
        acc[1][0] = ffma2(a1, bb.x, acc[1][0]); acc[1][1] = ffma2(a1, bb.y, acc[1][1]);
        acc[2][0] = ffma2(a2, bb.x, acc[2][0]); acc[2][1] = ffma2(a2, bb.y, acc[2][1]);
        acc[3][0] = ffma2(a3, bb.x, acc[3][0]); acc[3][1] = ffma2(a3, bb.y, acc[3][1]);
    }

    float* ag = g_A + ((size_t)bh * NNC + c) * ND * ND;
#pragma unroll
    for (int di = 0; di < 4; ++di) {
        float2 pA = up2(acc[di][0]);
        float2 pB = up2(acc[di][1]);
        *(float4*)&ag[(4 * ty + di) * ND + 4 * tx] = make_float4(pA.x, pA.y, pB.x, pB.y);
    }
}

// ---------------------------------------------------------------------------
// Kernel 2: prefix scan (PROVEN: 128 CTAs, float4, depth-8 pipeline).
// ---------------------------------------------------------------------------
__global__ __launch_bounds__(256)
void scan_kernel() {
    int blk = blockIdx.x;          // NBH*4
    int bh = blk >> 2;
    int qtr = blk & 3;
    int h = bh & (NH - 1);
    int tid = threadIdx.x;
    double lg = head_lg(h);
    float dec = (float)exp(lg * (double)NCK);

    size_t base = (size_t)bh * NNC * ND * ND + qtr * 1024 + tid * 4;

    float4 buf[8];
#pragma unroll
    for (int p = 0; p < 8; ++p)
        buf[p] = *(const float4*)(g_A + base + (size_t)p * ND * ND);

    float4 st = make_float4(0.f, 0.f, 0.f, 0.f);
#pragma unroll
    for (int c = 0; c < NNC; ++c) {
        *(float4*)(g_St + base + (size_t)c * ND * ND) = st;
        float4 a = buf[c & 7];
        if (c + 8 < NNC)
            buf[c & 7] = *(const float4*)(g_A + base + (size_t)(c + 8) * ND * ND);
        st.x = st.x * dec + a.x;
        st.y = st.y * dec + a.y;
        st.z = st.z * dec + a.z;
        st.w = st.w * dec + a.w;
    }
}

// ---------------------------------------------------------------------------
// Kernel 3: per-chunk output. 256 thr, 4 CTAs/SM, f32x2.
// NEW: Q staged transposed+swizzled (qsT[d][i]) and P written transposed
// (psT[j][i]) so the A-operand of ALL GEMMs is one LDS.128 per iteration.
// smem: qsT(4096) + ksT/psT(4096) + vs/sts(4352) + wq/wk(128) = 50688 B.
// ---------------------------------------------------------------------------
extern __shared__ float smC[];

__global__ __launch_bounds__(256, 4)
void passC_kernel(const float* __restrict__ V, float* __restrict__ out) {
    float* qsT = smC;                            // [d][i] swizzled, NCK*NCK
    float* ksT = smC + NCK * NCK;                // [d][j] swizzled; reused as psT[j][i]
    float* vs  = smC + 2 * NCK * NCK;            // [j][e] NCK*PST; reused as sts[d'][e]
    float* wq  = vs + NCK * PST;                 // [NCK] gamma^i
    float* wk  = wq + NCK;                       // [NCK] gamma^{-j}

    int c = blockIdx.x, h = blockIdx.y, b = blockIdx.z;
    int bh = b * NH + h;
    int tid = threadIdx.x;
    int c0 = c * NCK;

    if (tid < NCK) {
        double lg = head_lg(h);
        wq[tid] = (float)exp(lg * (double)tid);
        wk[tid] = (float)exp(-lg * (double)tid);
    }
    __syncthreads();

    const float* qg = g_qr + (bh * NS + c0) * ND;
    const float* kg = g_kr + (bh * NS + c0) * ND;
    const float* vg = V + (b * NS + c0) * NHID + h * ND;

#pragma unroll
    for (int t = 0; t < 16; ++t) {
        int idx = tid + t * 256;
        int r = idx >> 6, d = idx & 63;
        int sw = (((r >> 2) ^ (d & 15)) << 2) + (r & 3);
        qsT[d * NCK + sw] = qg[r * ND + d] * wq[r];
        ksT[d * NCK + sw] = kg[r * ND + d] * wk[r];
        vs[r * PST + d] = vg[r * NHID + d];
    }
    __syncthreads();

    int ty = tid >> 4, tx = tid & 15;
    int i0 = 4 * ty, j0 = 4 * tx;

    // ---- GEMM1: P = Q'.K'^T (f32x2, both operands LDS.128) ----
    u64 acc[4][2];
#pragma unroll
    for (int r = 0; r < 4; ++r) { acc[r][0] = 0ull; acc[r][1] = 0ull; }

#pragma unroll 8
    for (int d = 0; d < ND; ++d) {
        float4 qa = *(const float4*)&qsT[d * NCK + ((ty ^ (d & 15)) << 2)];
        u64 a0 = pk2(qa.x), a1 = pk2(qa.y), a2 = pk2(qa.z), a3 = pk2(qa.w);
        ulonglong2 kb = *(const ulonglong2*)&ksT[d * NCK + ((tx ^ (d & 15)) << 2)];
        acc[0][0] = ffma2(a0, kb.x, acc[0][0]); acc[0][1] = ffma2(a0, kb.y, acc[0][1]);
        acc[1][0] = ffma2(a1, kb.x, acc[1][0]); acc[1][1] = ffma2(a1, kb.y, acc[1][1]);
        acc[2][0] = ffma2(a2, kb.x, acc[2][0]); acc[2][1] = ffma2(a2, kb.y, acc[2][1]);
        acc[3][0] = ffma2(a3, kb.x, acc[3][0]); acc[3][1] = ffma2(a3, kb.y, acc[3][1]);
    }
    __syncthreads();   // done reading ksT

    // ---- mask + write P TRANSPOSED into ksT's space: psT[j][i] swizzled ----
    float* psT = ksT;
    {
        float pv[4][4];
#pragma unroll
        for (int r = 0; r < 4; ++r) {
            float2 a = up2(acc[r][0]);
            float2 bq = up2(acc[r][1]);
            pv[r][0] = a.x; pv[r][1] = a.y; pv[r][2] = bq.x; pv[r][3] = bq.y;
        }
#pragma unroll
        for (int jj = 0; jj < 4; ++jj) {
            int j = j0 + jj;
            float4 col;
            col.x = (j <= i0 + 0) ? pv[0][jj] : 0.0f;
            col.y = (j <= i0 + 1) ? pv[1][jj] : 0.0f;
            col.z = (j <= i0 + 2) ? pv[2][jj] : 0.0f;
            col.w = (j <= i0 + 3) ? pv[3][jj] : 0.0f;
            *(float4*)&psT[j * NCK + ((ty ^ (j & 15)) << 2)] = col;
        }
    }
    __syncthreads();

    // ---- GEMM2a: O = P.V (f32x2, A via psT LDS.128) ----
    u64 o[4][2];
#pragma unroll
    for (int r = 0; r < 4; ++r) { o[r][0] = 0ull; o[r][1] = 0ull; }

#pragma unroll 8
    for (int j = 0; j < NCK; ++j) {
        float4 pa = *(const float4*)&psT[j * NCK + ((ty ^ (j & 15)) << 2)];
        u64 a0 = pk2(pa.x), a1 = pk2(pa.y), a2 = pk2(pa.z), a3 = pk2(pa.w);
        ulonglong2 bb = *(const ulonglong2*)(vs + j * PST + j0);
        o[0][0] = ffma2(a0, bb.x, o[0][0]); o[0][1] = ffma2(a0, bb.y, o[0][1]);
        o[1][0] = ffma2(a1, bb.x, o[1][0]); o[1][1] = ffma2(a1, bb.y, o[1][1]);
        o[2][0] = ffma2(a2, bb.x, o[2][0]); o[2][1] = ffma2(a2, bb.y, o[2][1]);
        o[3][0] = ffma2(a3, bb.x, o[3][0]); o[3][1] = ffma2(a3, bb.y, o[3][1]);
    }
    __syncthreads();   // done reading vs

    // ---- stage St over vs ----
    {
        const float* stg = g_St + ((size_t)bh * NNC + c) * ND * ND;
#pragma unroll
        for (int t = 0; t < 16; ++t) {
            int idx = tid + t * 256;
            int r = idx >> 6, e = idx & 63;
            vs[r * PST + e] = stg[idx];
        }
    }
    __syncthreads();

    // ---- GEMM2b: O += Q'.St (f32x2, A via qsT LDS.128) ----
    float* sts = vs;
#pragma unroll 8
    for (int d = 0; d < ND; ++d) {
        float4 qa = *(const float4*)&qsT[d * NCK + ((ty ^ (d & 15)) << 2)];
        u64 a0 = pk2(qa.x), a1 = pk2(qa.y), a2 = pk2(qa.z), a3 = pk2(qa.w);
        ulonglong2 bb = *(const ulonglong2*)(sts + d * PST + j0);
        o[0][0] = ffma2(a0, bb.x, o[0][0]); o[0][1] = ffma2(a0, bb.y, o[0][1]);
        o[1][0] = ffma2(a1, bb.x, o[1][0]); o[1][1] = ffma2(a1, bb.y, o[1][1]);
        o[2][0] = ffma2(a2, bb.x, o[2][0]); o[2][1] = ffma2(a2, bb.y, o[2][1]);
        o[3][0] = ffma2(a3, bb.x, o[3][0]); o[3][1] = ffma2(a3, bb.y, o[3][1]);
    }

    float* og = out + ((size_t)(b * NS + c0)) * NHID + h * ND;
#pragma unroll
    for (int di = 0; di < 4; ++di) {
        float2 pA = up2(o[di][0]);
        float2 pB = up2(o[di][1]);
        *(float4*)&og[(size_t)(i0 + di) * NHID + j0] = make_float4(pA.x, pA.y, pB.x, pB.y);
    }
}

// ---------------------------------------------------------------------------
extern "C" void kernel_launch(void* const* d_in, const int* in_sizes, int n_in,
                              void* d_out, int out_size) {
    (void)in_sizes; (void)n_in; (void)out_size;
    const float* Q = (const float*)d_in[0];
    const float* K = (const float*)d_in[1];
    const float* V = (const float*)d_in[2];
    float* out = (float*)d_out;

    table_kernel<<<(NS * 32) / 256, 256>>>();
    rope_lite_kernel<<<(NBH * NS * 16) / 256, 256>>>(Q, K);

    dim3 grid(NNC, NH, NB);
    passA_kernel<<<grid, 256>>>(V);
    scan_kernel<<<NBH * 4, 256>>>();

    size_t shm = (size_t)(2 * NCK * NCK + NCK * PST + 2 * NCK) * sizeof(float);  // 50688 B
    cudaFuncSetAttribute(passC_kernel, cudaFuncAttributeMaxDynamicSharedMemorySize, (int)shm);
    passC_kernel<<<grid, 256, shm>>>(V, out);
}

// round 16
// speedup vs baseline: 1.1095x; 1.1095x over previous
#include <cuda_runtime.h>
#include <math.h>

// Problem constants
#define NB   2
#define NS   2048
#define NH   16
#define ND   64
#define NHID 1024
#define NCK  64      // chunk size
#define NNC  32      // chunks per sequence
#define NBH  32      // NB*NH
#define PST  68      // padded smem row stride (floats)

typedef unsigned long long u64;

// Scratch (static device globals -- no allocation allowed)
__device__ float4 g_tab[NS * 32];              // xPos table: (cos*sc, sin*sc, cos/sc, sin/sc)
__device__ float  g_A [NBH * NNC * ND * ND];   // per-chunk state contributions
__device__ float  g_St[NBH * NNC * ND * ND];   // prefix-scanned states (state BEFORE chunk c)

__device__ __forceinline__ double head_lg(int h) {
    const double L0 = -3.4657359027997265;   // log(1/32)
    const double L1 = -6.2383246250395075;   // log(1/512)
    double g = 1.0 - exp(L0 + (L1 - L0) * ((double)h / 15.0));
    return log(g);
}

// ---- packed f32x2 helpers ----
__device__ __forceinline__ u64 pk2(float x) {
    unsigned xi = __float_as_uint(x);
    u64 r; asm("mov.b64 %0, {%1, %1};" : "=l"(r) : "r"(xi)); return r;
}
__device__ __forceinline__ u64 ffma2(u64 a, u64 b, u64 c) {
    u64 d; asm("fma.rn.f32x2 %0, %1, %2, %3;" : "=l"(d) : "l"(a), "l"(b), "l"(c)); return d;
}
__device__ __forceinline__ float2 up2(u64 v) {
    unsigned lo, hi; asm("mov.b64 {%0, %1}, %2;" : "=r"(lo), "=r"(hi) : "l"(v));
    return make_float2(__uint_as_float(lo), __uint_as_float(hi));
}

// ---------------------------------------------------------------------------
// Kernel 0: xPos table. tab[s][i] = (cos*sc, sin*sc, cos/sc, sin/sc)
// ---------------------------------------------------------------------------
__global__ __launch_bounds__(256)
void table_kernel() {
    int idx = blockIdx.x * 256 + threadIdx.x;   // [0, 2048*32)
    int i = idx & 31;
    int s = idx >> 5;
    float invf = (float)(1.0 / pow(10000.0, (double)i / 32.0));
    float bs   = (2.0f * (float)i + 25.6f) / 89.6f;   // (2i + 0.4*64)/(1.4*64)
    float pos  = (float)s;
    float sn, cs;
    sincosf(pos * invf, &sn, &cs);
    float sc = powf(bs, pos * (1.0f / 512.0f));
    float iv = 1.0f / sc;
    g_tab[idx] = make_float4(cs * sc, sn * sc, cs * iv, sn * iv);
}

// ---------------------------------------------------------------------------
// Kernel 1: A_c[d][e] = sum_j gamma^(C-j) k'[j][d] v[j][e]
// Rotation fused via shfl-pair trick; staging index mapping IDENTICAL to the
// proven coalesced pattern (warp reads 32 consecutive floats of K/V).
// GEMM body byte-identical to R14 (f32x2, float4 A-load).
// ---------------------------------------------------------------------------
__global__ __launch_bounds__(256)
void passA_kernel(const float* __restrict__ K, const float* __restrict__ V) {
    __shared__ float ks[NCK * PST];
    __shared__ float vs[NCK * PST];
    __shared__ float wr[NCK];

    int c = blockIdx.x, h = blockIdx.y, b = blockIdx.z;
    int bh = b * NH + h;
    int tid = threadIdx.x;

    if (tid < NCK) {
        double lg = head_lg(h);
        wr[tid] = (float)exp(lg * (double)(NCK - tid));   // gamma^(C-j)
    }
    __syncthreads();

    int c0 = c * NCK;

#pragma unroll
    for (int t = 0; t < 16; ++t) {
        int idx = tid + t * 256;
        int r = idx >> 6, d = idx & 63;
        size_t ro = ((size_t)(b * NS + c0 + r)) * NHID + h * ND + d;
        float kv = K[ro];
        float vv = V[ro];
        float kp = __shfl_xor_sync(0xffffffffu, kv, 1);   // pair element (lane parity == d parity)
        float4 tb = g_tab[(size_t)(c0 + r) * 32 + (d >> 1)];
        float sgn = (d & 1) ? 1.0f : -1.0f;
        ks[r * PST + d] = (kv * tb.z + sgn * kp * tb.w) * wr[r];
        vs[r * PST + d] = vv;
    }
    __syncthreads();

    int ty = tid >> 4, tx = tid & 15;
    u64 acc[4][2];
#pragma unroll
    for (int r = 0; r < 4; ++r) { acc[r][0] = 0ull; acc[r][1] = 0ull; }

#pragma unroll 8
    for (int j = 0; j < NCK; ++j) {
        float4 ka = *(const float4*)(ks + j * PST + 4 * ty);
        u64 a0 = pk2(ka.x), a1 = pk2(ka.y), a2 = pk2(ka.z), a3 = pk2(ka.w);
        ulonglong2 bb = *(const ulonglong2*)(vs + j * PST + 4 * tx);
        acc[0][0] = ffma2(a0, bb.x, acc[0][0]); acc[0][1] = ffma2(a0, bb.y, acc[0][1]);
        acc[1][0] = ffma2(a1, bb.x, acc[1][0]); acc[1][1] = ffma2(a1, bb.y, acc[1][1]);
        acc[2][0] = ffma2(a2, bb.x, acc[2][0]); acc[2][1] = ffma2(a2, bb.y, acc[2][1]);
        acc[3][0] = ffma2(a3, bb.x, acc[3][0]); acc[3][1] = ffma2(a3, bb.y, acc[3][1]);
    }

    float* ag = g_A + ((size_t)bh * NNC + c) * ND * ND;
#pragma unroll
    for (int di = 0; di < 4; ++di) {
        float2 pA = up2(acc[di][0]);
        float2 pB = up2(acc[di][1]);
        *(float4*)&ag[(4 * ty + di) * ND + 4 * tx] = make_float4(pA.x, pA.y, pB.x, pB.y);
    }
}

// ---------------------------------------------------------------------------
// Kernel 2: prefix scan (PROVEN: 128 CTAs, float4, depth-8 pipeline).
// ---------------------------------------------------------------------------
__global__ __launch_bounds__(256)
void scan_kernel() {
    int blk = blockIdx.x;          // NBH*4
    int bh = blk >> 2;
    int qtr = blk & 3;
    int h = bh & (NH - 1);
    int tid = threadIdx.x;
    double lg = head_lg(h);
    float dec = (float)exp(lg * (double)NCK);

    size_t base = (size_t)bh * NNC * ND * ND + qtr * 1024 + tid * 4;

    float4 buf[8];
#pragma unroll
    for (int p = 0; p < 8; ++p)
        buf[p] = *(const float4*)(g_A + base + (size_t)p * ND * ND);

    float4 st = make_float4(0.f, 0.f, 0.f, 0.f);
#pragma unroll
    for (int c = 0; c < NNC; ++c) {
        *(float4*)(g_St + base + (size_t)c * ND * ND) = st;
        float4 a = buf[c & 7];
        if (c + 8 < NNC)
            buf[c & 7] = *(const float4*)(g_A + base + (size_t)(c + 8) * ND * ND);
        st.x = st.x * dec + a.x;
        st.y = st.y * dec + a.y;
        st.z = st.z * dec + a.z;
        st.w = st.w * dec + a.w;
    }
}

// ---------------------------------------------------------------------------
// Kernel 3: per-chunk output. R14-proven structure (256 thr, 4 CTAs/SM,
// f32x2, qs row-major + swizzled ksT + ps overlay + St-over-vs).
// Rotation fused via shfl-pair trick; staging mapping/store pattern identical.
// ---------------------------------------------------------------------------
extern __shared__ float smC[];

__global__ __launch_bounds__(256, 4)
void passC_kernel(const float* __restrict__ Q, const float* __restrict__ K,
                  const float* __restrict__ V, float* __restrict__ out) {
    float* qs  = smC;                            // [i][d]  NCK*PST
    float* ksT = smC + NCK * PST;                // [d][j] swizzled; reused as ps[i][j]
    float* vs  = smC + NCK * PST + NCK * NCK;    // [j][e]; reused as sts[d'][e]
    float* wq  = vs + NCK * PST;                 // [NCK] gamma^i
    float* wk  = wq + NCK;                       // [NCK] gamma^{-j}

    int c = blockIdx.x, h = blockIdx.y, b = blockIdx.z;
    int bh = b * NH + h;
    int tid = threadIdx.x;
    int c0 = c * NCK;

    if (tid < NCK) {
        double lg = head_lg(h);
        wq[tid] = (float)exp(lg * (double)tid);
        wk[tid] = (float)exp(-lg * (double)tid);
    }
    __syncthreads();

#pragma unroll
    for (int t = 0; t < 16; ++t) {
        int idx = tid + t * 256;
        int r = idx >> 6, d = idx & 63;
        size_t ro = ((size_t)(b * NS + c0 + r)) * NHID + h * ND + d;
        float qv = Q[ro];
        float kv = K[ro];
        float vv = V[ro];
        float qp = __shfl_xor_sync(0xffffffffu, qv, 1);
        float kp = __shfl_xor_sync(0xffffffffu, kv, 1);
        float4 tb = g_tab[(size_t)(c0 + r) * 32 + (d >> 1)];
        float sgn = (d & 1) ? 1.0f : -1.0f;
        qs[r * PST + d] = (qv * tb.x + sgn * qp * tb.y) * wq[r];
        float kr_ = (kv * tb.z + sgn * kp * tb.w) * wk[r];
        ksT[d * NCK + (((r >> 2) ^ (d & 15)) << 2) + (r & 3)] = kr_;
        vs[r * PST + d] = vv;
    }
    __syncthreads();

    int ty = tid >> 4, tx = tid & 15;
    int i0 = 4 * ty, j0 = 4 * tx;

    // ---- GEMM1: P = Q'.K'^T (f32x2) ----
    u64 acc[4][2];
#pragma unroll
    for (int r = 0; r < 4; ++r) { acc[r][0] = 0ull; acc[r][1] = 0ull; }

#pragma unroll 8
    for (int d = 0; d < ND; ++d) {
        u64 a0 = pk2(qs[(i0 + 0) * PST + d]);
        u64 a1 = pk2(qs[(i0 + 1) * PST + d]);
        u64 a2 = pk2(qs[(i0 + 2) * PST + d]);
        u64 a3 = pk2(qs[(i0 + 3) * PST + d]);
        ulonglong2 kb = *(const ulonglong2*)&ksT[d * NCK + ((tx ^ (d & 15)) << 2)];
        acc[0][0] = ffma2(a0, kb.x, acc[0][0]); acc[0][1] = ffma2(a0, kb.y, acc[0][1]);
        acc[1][0] = ffma2(a1, kb.x, acc[1][0]); acc[1][1] = ffma2(a1, kb.y, acc[1][1]);
        acc[2][0] = ffma2(a2, kb.x, acc[2][0]); acc[2][1] = ffma2(a2, kb.y, acc[2][1]);
        acc[3][0] = ffma2(a3, kb.x, acc[3][0]); acc[3][1] = ffma2(a3, kb.y, acc[3][1]);
    }
    __syncthreads();   // done reading ksT

    // ---- mask + stage P into ksT's space ----
    float* ps = ksT;
#pragma unroll
    for (int di = 0; di < 4; ++di) {
        int ii = i0 + di;
        float2 vA = up2(acc[di][0]);
        float2 vB = up2(acc[di][1]);
        float4 w;
        w.x = (j0 + 0 <= ii) ? vA.x : 0.0f;
        w.y = (j0 + 1 <= ii) ? vA.y : 0.0f;
        w.z = (j0 + 2 <= ii) ? vB.x : 0.0f;
        w.w = (j0 + 3 <= ii) ? vB.y : 0.0f;
        *(float4*)&ps[ii * NCK + j0] = w;
    }
    __syncthreads();

    // ---- GEMM2a: O = P.V (f32x2) ----
    u64 o[4][2];
#pragma unroll
    for (int r = 0; r < 4; ++r) { o[r][0] = 0ull; o[r][1] = 0ull; }

#pragma unroll 8
    for (int j = 0; j < NCK; ++j) {
        u64 a0 = pk2(ps[(i0 + 0) * NCK + j]);
        u64 a1 = pk2(ps[(i0 + 1) * NCK + j]);
        u64 a2 = pk2(ps[(i0 + 2) * NCK + j]);
        u64 a3 = pk2(ps[(i0 + 3) * NCK + j]);
        ulonglong2 bb = *(const ulonglong2*)(vs + j * PST + j0);
        o[0][0] = ffma2(a0, bb.x, o[0][0]); o[0][1] = ffma2(a0, bb.y, o[0][1]);
        o[1][0] = ffma2(a1, bb.x, o[1][0]); o[1][1] = ffma2(a1, bb.y, o[1][1]);
        o[2][0] = ffma2(a2, bb.x, o[2][0]); o[2][1] = ffma2(a2, bb.y, o[2][1]);
        o[3][0] = ffma2(a3, bb.x, o[3][0]); o[3][1] = ffma2(a3, bb.y, o[3][1]);
    }
    __syncthreads();   // done reading vs

    // ---- stage St over vs ----
    {
        const float* stg = g_St + ((size_t)bh * NNC + c) * ND * ND;
#pragma unroll
        for (int t = 0; t < 16; ++t) {
            int idx = tid + t * 256;
            int r = idx >> 6, e = idx & 63;
            vs[r * PST + e] = stg[idx];
        }
    }
    __syncthreads();

    // ---- GEMM2b: O += Q'.St (f32x2) ----
    float* sts = vs;
#pragma unroll 8
    for (int d = 0; d < ND; ++d) {
        u64 a0 = pk2(qs[(i0 + 0) * PST + d]);
        u64 a1 = pk2(qs[(i0 + 1) * PST + d]);
        u64 a2 = pk2(qs[(i0 + 2) * PST + d]);
        u64 a3 = pk2(qs[(i0 + 3) * PST + d]);
        ulonglong2 bb = *(const ulonglong2*)(sts + d * PST + j0);
        o[0][0] = ffma2(a0, bb.x, o[0][0]); o[0][1] = ffma2(a0, bb.y, o[0][1]);
        o[1][0] = ffma2(a1, bb.x, o[1][0]); o[1][1] = ffma2(a1, bb.y, o[1][1]);
        o[2][0] = ffma2(a2, bb.x, o[2][0]); o[2][1] = ffma2(a2, bb.y, o[2][1]);
        o[3][0] = ffma2(a3, bb.x, o[3][0]); o[3][1] = ffma2(a3, bb.y, o[3][1]);
    }

    float* og = out + ((size_t)(b * NS + c0)) * NHID + h * ND;
#pragma unroll
    for (int di = 0; di < 4; ++di) {
        float2 pA = up2(o[di][0]);
        float2 pB = up2(o[di][1]);
        *(float4*)&og[(size_t)(i0 + di) * NHID + j0] = make_float4(pA.x, pA.y, pB.x, pB.y);
    }
}

// ---------------------------------------------------------------------------
extern "C" void kernel_launch(void* const* d_in, const int* in_sizes, int n_in,
                              void* d_out, int out_size) {
    (void)in_sizes; (void)n_in; (void)out_size;
    const float* Q = (const float*)d_in[0];
    const float* K = (const float*)d_in[1];
    const float* V = (const float*)d_in[2];
    float* out = (float*)d_out;

    table_kernel<<<(NS * 32) / 256, 256>>>();

    dim3 grid(NNC, NH, NB);
    passA_kernel<<<grid, 256>>>(K, V);
    scan_kernel<<<NBH * 4, 256>>>();

    size_t shm = (size_t)(2 * NCK * PST + NCK * NCK + 2 * NCK) * sizeof(float);  // 51712 B
    cudaFuncSetAttribute(passC_kernel, cudaFuncAttributeMaxDynamicSharedMemorySize, (int)shm);
    passC_kernel<<<grid, 256, shm>>>(Q, K, V, out);
}

// round 17
// speedup vs baseline: 1.1167x; 1.0065x over previous
#include <cuda_runtime.h>
#include <math.h>

// Problem constants
#define NB   2
#define NS   2048
#define NH   16
#define ND   64
#define NHID 1024
#define NCK  64      // chunk size
#define NNC  32      // chunks per sequence
#define NBH  32      // NB*NH
#define PST  68      // padded smem row stride (floats)

typedef unsigned long long u64;

// Scratch (static device globals -- no allocation allowed)
__device__ float4 g_tab[NS * 32];              // xPos table: (cos*sc, sin*sc, cos/sc, sin/sc)
__device__ float  g_A [NBH * NNC * ND * ND];   // per-chunk state contributions
__device__ float  g_St[NBH * NNC * ND * ND];   // prefix-scanned states (state BEFORE chunk c)

__device__ __forceinline__ double head_lg(int h) {
    const double L0 = -3.4657359027997265;   // log(1/32)
    const double L1 = -6.2383246250395075;   // log(1/512)
    double g = 1.0 - exp(L0 + (L1 - L0) * ((double)h / 15.0));
    return log(g);
}

// ---- packed f32x2 helpers ----
__device__ __forceinline__ u64 pk2(float x) {
    unsigned xi = __float_as_uint(x);
    u64 r; asm("mov.b64 %0, {%1, %1};" : "=l"(r) : "r"(xi)); return r;
}
__device__ __forceinline__ u64 ffma2(u64 a, u64 b, u64 c) {
    u64 d; asm("fma.rn.f32x2 %0, %1, %2, %3;" : "=l"(d) : "l"(a), "l"(b), "l"(c)); return d;
}
__device__ __forceinline__ float2 up2(u64 v) {
    unsigned lo, hi; asm("mov.b64 {%0, %1}, %2;" : "=r"(lo), "=r"(hi) : "l"(v));
    return make_float2(__uint_as_float(lo), __uint_as_float(hi));
}

// ---------------------------------------------------------------------------
// Kernel 0: xPos table. tab[s][i] = (cos*sc, sin*sc, cos/sc, sin/sc)
// ---------------------------------------------------------------------------
__global__ __launch_bounds__(256)
void table_kernel() {
    int idx = blockIdx.x * 256 + threadIdx.x;   // [0, 2048*32)
    int i = idx & 31;
    int s = idx >> 5;
    float invf = (float)(1.0 / pow(10000.0, (double)i / 32.0));
    float bs   = (2.0f * (float)i + 25.6f) / 89.6f;   // (2i + 0.4*64)/(1.4*64)
    float pos  = (float)s;
    float sn, cs;
    sincosf(pos * invf, &sn, &cs);
    float sc = powf(bs, pos * (1.0f / 512.0f));
    float iv = 1.0f / sc;
    g_tab[idx] = make_float4(cs * sc, sn * sc, cs * iv, sn * iv);
}

// ---------------------------------------------------------------------------
// Kernel 1: A_c[d][e] = sum_j gamma^(C-j) k'[j][d] v[j][e]
// Shfl-fused rotation (proven R16); f32x2 GEMM body (proven R14/15).
// ---------------------------------------------------------------------------
__global__ __launch_bounds__(256)
void passA_kernel(const float* __restrict__ K, const float* __restrict__ V) {
    __shared__ float ks[NCK * PST];
    __shared__ float vs[NCK * PST];
    __shared__ float wr[NCK];

    int c = blockIdx.x, h = blockIdx.y, b = blockIdx.z;
    int bh = b * NH + h;
    int tid = threadIdx.x;

    if (tid < NCK) {
        double lg = head_lg(h);
        wr[tid] = (float)exp(lg * (double)(NCK - tid));   // gamma^(C-j)
    }
    __syncthreads();

    int c0 = c * NCK;

#pragma unroll
    for (int t = 0; t < 16; ++t) {
        int idx = tid + t * 256;
        int r = idx >> 6, d = idx & 63;
        size_t ro = ((size_t)(b * NS + c0 + r)) * NHID + h * ND + d;
        float kv = K[ro];
        float vv = V[ro];
        float kp = __shfl_xor_sync(0xffffffffu, kv, 1);   // pair element
        float4 tb = g_tab[(size_t)(c0 + r) * 32 + (d >> 1)];
        float sgn = (d & 1) ? 1.0f : -1.0f;
        ks[r * PST + d] = (kv * tb.z + sgn * kp * tb.w) * wr[r];
        vs[r * PST + d] = vv;
    }
    __syncthreads();

    int ty = tid >> 4, tx = tid & 15;
    u64 acc[4][2];
#pragma unroll
    for (int r = 0; r < 4; ++r) { acc[r][0] = 0ull; acc[r][1] = 0ull; }

#pragma unroll 8
    for (int j = 0; j < NCK; ++j) {
        float4 ka = *(const float4*)(ks + j * PST + 4 * ty);
        u64 a0 = pk2(ka.x), a1 = pk2(ka.y), a2 = pk2(ka.z), a3 = pk2(ka.w);
        ulonglong2 bb = *(const ulonglong2*)(vs + j * PST + 4 * tx);
        acc[0][0] = ffma2(a0, bb.x, acc[0][0]); acc[0][1] = ffma2(a0, bb.y, acc[0][1]);
        acc[1][0] = ffma2(a1, bb.x, acc[1][0]); acc[1][1] = ffma2(a1, bb.y, acc[1][1]);
        acc[2][0] = ffma2(a2, bb.x, acc[2][0]); acc[2][1] = ffma2(a2, bb.y, acc[2][1]);
        acc[3][0] = ffma2(a3, bb.x, acc[3][0]); acc[3][1] = ffma2(a3, bb.y, acc[3][1]);
    }

    float* ag = g_A + ((size_t)bh * NNC + c) * ND * ND;
#pragma unroll
    for (int di = 0; di < 4; ++di) {
        float2 pA = up2(acc[di][0]);
        float2 pB = up2(acc[di][1]);
        *(float4*)&ag[(4 * ty + di) * ND + 4 * tx] = make_float4(pA.x, pA.y, pB.x, pB.y);
    }
}

// ---------------------------------------------------------------------------
// Kernel 2: prefix scan (PROVEN: 128 CTAs, float4, depth-8 pipeline).
// ---------------------------------------------------------------------------
__global__ __launch_bounds__(256)
void scan_kernel() {
    int blk = blockIdx.x;          // NBH*4
    int bh = blk >> 2;
    int qtr = blk & 3;
    int h = bh & (NH - 1);
    int tid = threadIdx.x;
    double lg = head_lg(h);
    float dec = (float)exp(lg * (double)NCK);

    size_t base = (size_t)bh * NNC * ND * ND + qtr * 1024 + tid * 4;

    float4 buf[8];
#pragma unroll
    for (int p = 0; p < 8; ++p)
        buf[p] = *(const float4*)(g_A + base + (size_t)p * ND * ND);

    float4 st = make_float4(0.f, 0.f, 0.f, 0.f);
#pragma unroll
    for (int c = 0; c < NNC; ++c) {
        *(float4*)(g_St + base + (size_t)c * ND * ND) = st;
        float4 a = buf[c & 7];
        if (c + 8 < NNC)
            buf[c & 7] = *(const float4*)(g_A + base + (size_t)(c + 8) * ND * ND);
        st.x = st.x * dec + a.x;
        st.y = st.y * dec + a.y;
        st.z = st.z * dec + a.z;
        st.w = st.w * dec + a.w;
    }
}

// ---------------------------------------------------------------------------
// Kernel 3: per-chunk output. R16-proven staging + structure; inner loops
// d-pair unrolled with float2 a-loads; ps padded to stride PST (bank fix).
// smem: qs(4352) + ksT/ps(4352) + vs/sts(4352) + wq/wk(128) = 52736 B.
// ---------------------------------------------------------------------------
extern __shared__ float smC[];

__global__ __launch_bounds__(256, 4)
void passC_kernel(const float* __restrict__ Q, const float* __restrict__ K,
                  const float* __restrict__ V, float* __restrict__ out) {
    float* qs  = smC;                            // [i][d]  stride PST
    float* ksT = smC + NCK * PST;                // [d][j] swizzled (stride NCK); reused as ps[i][j] stride PST
    float* vs  = smC + 2 * NCK * PST;            // [j][e] stride PST; reused as sts[d'][e]
    float* wq  = vs + NCK * PST;                 // [NCK] gamma^i
    float* wk  = wq + NCK;                       // [NCK] gamma^{-j}

    int c = blockIdx.x, h = blockIdx.y, b = blockIdx.z;
    int bh = b * NH + h;
    int tid = threadIdx.x;
    int c0 = c * NCK;

    if (tid < NCK) {
        double lg = head_lg(h);
        wq[tid] = (float)exp(lg * (double)tid);
        wk[tid] = (float)exp(-lg * (double)tid);
    }
    __syncthreads();

#pragma unroll
    for (int t = 0; t < 16; ++t) {
        int idx = tid + t * 256;
        int r = idx >> 6, d = idx & 63;
        size_t ro = ((size_t)(b * NS + c0 + r)) * NHID + h * ND + d;
        float qv = Q[ro];
        float kv = K[ro];
        float vv = V[ro];
        float qp = __shfl_xor_sync(0xffffffffu, qv, 1);
        float kp = __shfl_xor_sync(0xffffffffu, kv, 1);
        float4 tb = g_tab[(size_t)(c0 + r) * 32 + (d >> 1)];
        float sgn = (d & 1) ? 1.0f : -1.0f;
        qs[r * PST + d] = (qv * tb.x + sgn * qp * tb.y) * wq[r];
        float kr_ = (kv * tb.z + sgn * kp * tb.w) * wk[r];
        ksT[d * NCK + (((r >> 2) ^ (d & 15)) << 2) + (r & 3)] = kr_;
        vs[r * PST + d] = vv;
    }
    __syncthreads();

    int ty = tid >> 4, tx = tid & 15;
    int i0 = 4 * ty, j0 = 4 * tx;

    // ---- GEMM1: P = Q'.K'^T (f32x2, d-pair unroll, float2 a-loads) ----
    u64 acc[4][2];
#pragma unroll
    for (int r = 0; r < 4; ++r) { acc[r][0] = 0ull; acc[r][1] = 0ull; }

#pragma unroll 4
    for (int d = 0; d < ND; d += 2) {
        float2 q0 = *(const float2*)(qs + (i0 + 0) * PST + d);
        float2 q1 = *(const float2*)(qs + (i0 + 1) * PST + d);
        float2 q2 = *(const float2*)(qs + (i0 + 2) * PST + d);
        float2 q3 = *(const float2*)(qs + (i0 + 3) * PST + d);
        ulonglong2 kb0 = *(const ulonglong2*)&ksT[(d + 0) * NCK + ((tx ^ ((d + 0) & 15)) << 2)];
        ulonglong2 kb1 = *(const ulonglong2*)&ksT[(d + 1) * NCK + ((tx ^ ((d + 1) & 15)) << 2)];
        u64 a;
        a = pk2(q0.x); acc[0][0] = ffma2(a, kb0.x, acc[0][0]); acc[0][1] = ffma2(a, kb0.y, acc[0][1]);
        a = pk2(q0.y); acc[0][0] = ffma2(a, kb1.x, acc[0][0]); acc[0][1] = ffma2(a, kb1.y, acc[0][1]);
        a = pk2(q1.x); acc[1][0] = ffma2(a, kb0.x, acc[1][0]); acc[1][1] = ffma2(a, kb0.y, acc[1][1]);
        a = pk2(q1.y); acc[1][0] = ffma2(a, kb1.x, acc[1][0]); acc[1][1] = ffma2(a, kb1.y, acc[1][1]);
        a = pk2(q2.x); acc[2][0] = ffma2(a, kb0.x, acc[2][0]); acc[2][1] = ffma2(a, kb0.y, acc[2][1]);
        a = pk2(q2.y); acc[2][0] = ffma2(a, kb1.x, acc[2][0]); acc[2][1] = ffma2(a, kb1.y, acc[2][1]);
        a = pk2(q3.x); acc[3][0] = ffma2(a, kb0.x, acc[3][0]); acc[3][1] = ffma2(a, kb0.y, acc[3][1]);
        a = pk2(q3.y); acc[3][0] = ffma2(a, kb1.x, acc[3][0]); acc[3][1] = ffma2(a, kb1.y, acc[3][1]);
    }
    __syncthreads();   // done reading ksT

    // ---- mask + stage P into ksT's space (stride PST: bank-conflict fix) ----
    float* ps = ksT;
#pragma unroll
    for (int di = 0; di < 4; ++di) {
        int ii = i0 + di;
        float2 vA = up2(acc[di][0]);
        float2 vB = up2(acc[di][1]);
        float4 w;
        w.x = (j0 + 0 <= ii) ? vA.x : 0.0f;
        w.y = (j0 + 1 <= ii) ? vA.y : 0.0f;
        w.z = (j0 + 2 <= ii) ? vB.x : 0.0f;
        w.w = (j0 + 3 <= ii) ? vB.y : 0.0f;
        *(float4*)&ps[ii * PST + j0] = w;
    }
    __syncthreads();

    // ---- GEMM2a: O = P.V (f32x2, j-pair unroll, float2 a-loads) ----
    u64 o[4][2];
#pragma unroll
    for (int r = 0; r < 4; ++r) { o[r][0] = 0ull; o[r][1] = 0ull; }

#pragma unroll 4
    for (int j = 0; j < NCK; j += 2) {
        float2 p0 = *(const float2*)(ps + (i0 + 0) * PST + j);
        float2 p1 = *(const float2*)(ps + (i0 + 1) * PST + j);
        float2 p2 = *(const float2*)(ps + (i0 + 2) * PST + j);
        float2 p3 = *(const float2*)(ps + (i0 + 3) * PST + j);
        ulonglong2 b0 = *(const ulonglong2*)(vs + (j + 0) * PST + j0);
        ulonglong2 b1 = *(const ulonglong2*)(vs + (j + 1) * PST + j0);
        u64 a;
        a = pk2(p0.x); o[0][0] = ffma2(a, b0.x, o[0][0]); o[0][1] = ffma2(a, b0.y, o[0][1]);
        a = pk2(p0.y); o[0][0] = ffma2(a, b1.x, o[0][0]); o[0][1] = ffma2(a, b1.y, o[0][1]);
        a = pk2(p1.x); o[1][0] = ffma2(a, b0.x, o[1][0]); o[1][1] = ffma2(a, b0.y, o[1][1]);
        a = pk2(p1.y); o[1][0] = ffma2(a, b1.x, o[1][0]); o[1][1] = ffma2(a, b1.y, o[1][1]);
        a = pk2(p2.x); o[2][0] = ffma2(a, b0.x, o[2][0]); o[2][1] = ffma2(a, b0.y, o[2][1]);
        a = pk2(p2.y); o[2][0] = ffma2(a, b1.x, o[2][0]); o[2][1] = ffma2(a, b1.y, o[2][1]);
        a = pk2(p3.x); o[3][0] = ffma2(a, b0.x, o[3][0]); o[3][1] = ffma2(a, b0.y, o[3][1]);
        a = pk2(p3.y); o[3][0] = ffma2(a, b1.x, o[3][0]); o[3][1] = ffma2(a, b1.y, o[3][1]);
    }
    __syncthreads();   // done reading vs

    // ---- stage St over vs ----
    {
        const float* stg = g_St + ((size_t)bh * NNC + c) * ND * ND;
#pragma unroll
        for (int t = 0; t < 16; ++t) {
            int idx = tid + t * 256;
            int r = idx >> 6, e = idx & 63;
            vs[r * PST + e] = stg[idx];
        }
    }
    __syncthreads();

    // ---- GEMM2b: O += Q'.St (f32x2, d-pair unroll, float2 a-loads) ----
    float* sts = vs;
#pragma unroll 4
    for (int d = 0; d < ND; d += 2) {
        float2 q0 = *(const float2*)(qs + (i0 + 0) * PST + d);
        float2 q1 = *(const float2*)(qs + (i0 + 1) * PST + d);
        float2 q2 = *(const float2*)(qs + (i0 + 2) * PST + d);
        float2 q3 = *(const float2*)(qs + (i0 + 3) * PST + d);
        ulonglong2 s0 = *(const ulonglong2*)(sts + (d + 0) * PST + j0);
        ulonglong2 s1 = *(const ulonglong2*)(sts + (d + 1) * PST + j0);
        u64 a;
        a = pk2(q0.x); o[0][0] = ffma2(a, s0.x, o[0][0]); o[0][1] = ffma2(a, s0.y, o[0][1]);
        a = pk2(q0.y); o[0][0] = ffma2(a, s1.x, o[0][0]); o[0][1] = ffma2(a, s1.y, o[0][1]);
        a = pk2(q1.x); o[1][0] = ffma2(a, s0.x, o[1][0]); o[1][1] = ffma2(a, s0.y, o[1][1]);
        a = pk2(q1.y); o[1][0] = ffma2(a, s1.x, o[1][0]); o[1][1] = ffma2(a, s1.y, o[1][1]);
        a = pk2(q2.x); o[2][0] = ffma2(a, s0.x, o[2][0]); o[2][1] = ffma2(a, s0.y, o[2][1]);
        a = pk2(q2.y); o[2][0] = ffma2(a, s1.x, o[2][0]); o[2][1] = ffma2(a, s1.y, o[2][1]);
        a = pk2(q3.x); o[3][0] = ffma2(a, s0.x, o[3][0]); o[3][1] = ffma2(a, s0.y, o[3][1]);
        a = pk2(q3.y); o[3][0] = ffma2(a, s1.x, o[3][0]); o[3][1] = ffma2(a, s1.y, o[3][1]);
    }

    float* og = out + ((size_t)(b * NS + c0)) * NHID + h * ND;
#pragma unroll
    for (int di = 0; di < 4; ++di) {
        float2 pA = up2(o[di][0]);
        float2 pB = up2(o[di][1]);
        *(float4*)&og[(size_t)(i0 + di) * NHID + j0] = make_float4(pA.x, pA.y, pB.x, pB.y);
    }
}

// ---------------------------------------------------------------------------
extern "C" void kernel_launch(void* const* d_in, const int* in_sizes, int n_in,
                              void* d_out, int out_size) {
    (void)in_sizes; (void)n_in; (void)out_size;
    const float* Q = (const float*)d_in[0];
    const float* K = (const float*)d_in[1];
    const float* V = (const float*)d_in[2];
    float* out = (float*)d_out;

    table_kernel<<<(NS * 32) / 256, 256>>>();

    dim3 grid(NNC, NH, NB);
    passA_kernel<<<grid, 256>>>(K, V);
    scan_kernel<<<NBH * 4, 256>>>();

    size_t shm = (size_t)(3 * NCK * PST + 2 * NCK) * sizeof(float);   // 52736 B
    cudaFuncSetAttribute(passC_kernel, cudaFuncAttributeMaxDynamicSharedMemorySize, (int)shm);
    passC_kernel<<<grid, 256, shm>>>(Q, K, V, out);
}